// round 2
// baseline (speedup 1.0000x reference)
#include <cuda_runtime.h>
#include <cuda_bf16.h>
#include <math.h>

// ---------------- model dims ----------------
#define BATCH 32
#define SEQ   257          // 256 patches + 1 cls
#define EMBED 1024
#define HEADS 16
#define HDIM  64
#define NB    12
#define HID   2816
#define TOK   (BATCH*SEQ)  // 8224
#define PTOK  (BATCH*256)  // 8192

// ---------------- scratch (device globals; no allocation allowed) ----------------
__device__ float  g_h  [TOK * EMBED];
__device__ float  g_a  [TOK * EMBED];
__device__ float  g_qkv[TOK * 3 * EMBED];
__device__ float  g_ao [TOK * EMBED];
__device__ float  g_u  [TOK * HID];
__device__ float  g_v  [TOK * HID];
__device__ float2 g_fc [SEQ * 32];

// ---------------- helpers ----------------
__device__ __forceinline__ float block_reduce_sum(float v, float* red) {
    int tid = threadIdx.x;
    #pragma unroll
    for (int o = 16; o; o >>= 1) v += __shfl_xor_sync(0xffffffffu, v, o);
    if ((tid & 31) == 0) red[tid >> 5] = v;
    __syncthreads();
    if (tid < 8) {
        float w = red[tid];
        #pragma unroll
        for (int o = 4; o; o >>= 1) w += __shfl_xor_sync(0xffu, w, o);
        if (tid == 0) red[0] = w;
    }
    __syncthreads();
    float r = red[0];
    __syncthreads();
    return r;
}

// ---------------- SGEMM: C[M,N] = A[M,K] @ B[K,N] (+C if ACC) ----------------
// 128x128 tile, BK=8, 256 threads, 8x8 per-thread micro-tile.
template<bool ACC>
__global__ __launch_bounds__(256)
void sgemm(const float* __restrict__ A, const float* __restrict__ B,
           float* __restrict__ C, int M, int N, int K) {
    __shared__ float As[8 * 128];
    __shared__ float Bs[8 * 128];

    const int tid = threadIdx.x;
    const int bm = blockIdx.y * 128;
    const int bn = blockIdx.x * 128;

    // A load mapping: row = tid/2 (0..127), kcol = (tid%2)*4
    const int a_row  = tid >> 1;
    const int a_kcol = (tid & 1) * 4;
    // B load mapping: krow = tid/32 (0..7), col = (tid%32)*4
    const int b_krow = tid >> 5;
    const int b_col  = (tid & 31) * 4;

    const int m0 = (tid >> 4) * 8;   // 0..120
    const int n0 = (tid & 15) * 8;   // 0..120

    float acc[8][8];
    #pragma unroll
    for (int i = 0; i < 8; i++)
        #pragma unroll
        for (int j = 0; j < 8; j++) acc[i][j] = 0.f;

    const bool a_ok = (bm + a_row) < M;
    const bool b_ok = (bn + b_col) < N;

    const int ksteps = K >> 3;
    for (int kt = 0; kt < ksteps; kt++) {
        // load A tile (transposed into As[k][m])
        float4 av = make_float4(0.f, 0.f, 0.f, 0.f);
        if (a_ok) av = *(const float4*)(A + (size_t)(bm + a_row) * K + kt * 8 + a_kcol);
        As[(a_kcol + 0) * 128 + a_row] = av.x;
        As[(a_kcol + 1) * 128 + a_row] = av.y;
        As[(a_kcol + 2) * 128 + a_row] = av.z;
        As[(a_kcol + 3) * 128 + a_row] = av.w;
        // load B tile
        float4 bv = make_float4(0.f, 0.f, 0.f, 0.f);
        if (b_ok) bv = *(const float4*)(B + (size_t)(kt * 8 + b_krow) * N + bn + b_col);
        *(float4*)(Bs + b_krow * 128 + b_col) = bv;
        __syncthreads();

        #pragma unroll
        for (int kk = 0; kk < 8; kk++) {
            float4 a0 = *(const float4*)(As + kk * 128 + m0);
            float4 a1 = *(const float4*)(As + kk * 128 + m0 + 4);
            float4 b0 = *(const float4*)(Bs + kk * 128 + n0);
            float4 b1 = *(const float4*)(Bs + kk * 128 + n0 + 4);
            float ar[8] = {a0.x, a0.y, a0.z, a0.w, a1.x, a1.y, a1.z, a1.w};
            float br[8] = {b0.x, b0.y, b0.z, b0.w, b1.x, b1.y, b1.z, b1.w};
            #pragma unroll
            for (int i = 0; i < 8; i++)
                #pragma unroll
                for (int j = 0; j < 8; j++)
                    acc[i][j] = fmaf(ar[i], br[j], acc[i][j]);
        }
        __syncthreads();
    }

    #pragma unroll
    for (int i = 0; i < 8; i++) {
        int m = bm + m0 + i;
        if (m < M) {
            float* cp = C + (size_t)m * N + bn + n0;
            if (ACC) {
                float4 c0 = *(float4*)cp;
                float4 c1 = *(float4*)(cp + 4);
                c0.x += acc[i][0]; c0.y += acc[i][1]; c0.z += acc[i][2]; c0.w += acc[i][3];
                c1.x += acc[i][4]; c1.y += acc[i][5]; c1.z += acc[i][6]; c1.w += acc[i][7];
                *(float4*)cp = c0; *(float4*)(cp + 4) = c1;
            } else {
                *(float4*)cp       = make_float4(acc[i][0], acc[i][1], acc[i][2], acc[i][3]);
                *(float4*)(cp + 4) = make_float4(acc[i][4], acc[i][5], acc[i][6], acc[i][7]);
            }
        }
    }
}

// ---------------- freqs_cis table ----------------
__global__ void fc_kernel(float2* __restrict__ fc) {
    int idx = blockIdx.x * blockDim.x + threadIdx.x;
    if (idx >= SEQ * 32) return;
    int s = idx / 32, i = idx % 32;
    if (s == 0) { fc[idx] = make_float2(0.f, 0.f); return; }
    int sp = s - 1;
    int gy = sp / 16, gx = sp % 16;
    int j   = (i < 16) ? i  : i - 16;
    int pos = (i < 16) ? gy : gx;
    float fr  = powf(10000.f, -(float)j / 16.f);
    float ang = (float)pos * fr;
    fc[idx] = make_float2(cosf(ang), sinf(ang));
}

// ---------------- assemble (patch+cond+pos) then LayerNorm ----------------
__global__ __launch_bounds__(256)
void assemble_ln(const float* __restrict__ tmpA, const float* __restrict__ tmpC,
                 const float* __restrict__ patch_b, const float* __restrict__ cond_b,
                 const float* __restrict__ pos, const float* __restrict__ g,
                 const float* __restrict__ bb, float* __restrict__ h) {
    __shared__ float red[8];
    int t = blockIdx.x;
    int b = t / SEQ, s = t % SEQ;
    int tid = threadIdx.x;
    float4 v;
    if (s == 0) {
        v = *((const float4*)(tmpC + (size_t)b * EMBED) + tid);
        float4 cb = ((const float4*)cond_b)[tid];
        v.x += cb.x; v.y += cb.y; v.z += cb.z; v.w += cb.w;
    } else {
        v = *((const float4*)(tmpA + (size_t)(b * 256 + s - 1) * EMBED) + tid);
        float4 pb = ((const float4*)patch_b)[tid];
        v.x += pb.x; v.y += pb.y; v.z += pb.z; v.w += pb.w;
    }
    float4 pe = *((const float4*)(pos + (size_t)s * EMBED) + tid);
    v.x += pe.x; v.y += pe.y; v.z += pe.z; v.w += pe.w;

    float sum  = block_reduce_sum(v.x + v.y + v.z + v.w, red);
    float mean = sum * (1.f / EMBED);
    float dx = v.x - mean, dy = v.y - mean, dz = v.z - mean, dw = v.w - mean;
    float ss  = block_reduce_sum(dx * dx + dy * dy + dz * dz + dw * dw, red);
    float r   = rsqrtf(ss * (1.f / EMBED) + 1e-6f);
    float4 gv = ((const float4*)g)[tid];
    float4 bv = ((const float4*)bb)[tid];
    float4 o  = make_float4(dx * r * gv.x + bv.x, dy * r * gv.y + bv.y,
                            dz * r * gv.z + bv.z, dw * r * gv.w + bv.w);
    *((float4*)(h + (size_t)t * EMBED) + tid) = o;
}

// ---------------- RMSNorm ----------------
__global__ __launch_bounds__(256)
void rmsnorm_kernel(const float* __restrict__ h, const float* __restrict__ w,
                    float* __restrict__ out) {
    __shared__ float red[8];
    int t = blockIdx.x, tid = threadIdx.x;
    float4 v = *((const float4*)(h + (size_t)t * EMBED) + tid);
    float ss = block_reduce_sum(v.x * v.x + v.y * v.y + v.z * v.z + v.w * v.w, red);
    float r  = rsqrtf(ss * (1.f / EMBED) + 1e-5f);
    float4 wv = ((const float4*)w)[tid];
    float4 o  = make_float4(v.x * r * wv.x, v.y * r * wv.y, v.z * r * wv.z, v.w * r * wv.w);
    *((float4*)(out + (size_t)t * EMBED) + tid) = o;
}

// ---------------- RoPE applied in-place to q,k parts of qkv ----------------
__global__ void rope_kernel(float* __restrict__ qkv, const float2* __restrict__ fc) {
    int idx = blockIdx.x * blockDim.x + threadIdx.x;
    if (idx >= TOK * 512) return;
    int t = idx >> 9;
    int r = idx & 511;
    int head = r >> 5, pair = r & 31;
    int s = t % SEQ;
    float2 cs = fc[s * 32 + pair];
    size_t base = (size_t)t * (3 * EMBED) + head * HDIM + pair * 2;
    float2* qp = (float2*)(qkv + base);
    float2 xv = *qp;
    *qp = make_float2(xv.x * cs.x - xv.y * cs.y, xv.y * cs.x + xv.x * cs.y);
    float2* kp = (float2*)(qkv + base + EMBED);
    xv = *kp;
    *kp = make_float2(xv.x * cs.x - xv.y * cs.y, xv.y * cs.x + xv.x * cs.y);
}

// ---------------- attention: one CTA per (b,h), K/V resident in smem ----------------
#define KV_STRIDE 65
#define ATTN_SMEM ((2 * SEQ * KV_STRIDE + 8 * HDIM) * 4)

__global__ __launch_bounds__(256)
void attn_kernel(const float* __restrict__ qkv, float* __restrict__ out) {
    extern __shared__ float sm[];
    float* Ks = sm;
    float* Vs = sm + SEQ * KV_STRIDE;
    float* Qs = Vs + SEQ * KV_STRIDE;

    const int h = blockIdx.x;
    const int b = blockIdx.y;
    const int tid = threadIdx.x;

    // cooperative K/V load
    for (int i = tid; i < SEQ * HDIM; i += 256) {
        int t = i >> 6, d = i & 63;
        size_t row = (size_t)(b * SEQ + t) * (3 * EMBED) + h * HDIM + d;
        Ks[t * KV_STRIDE + d] = qkv[row + EMBED];
        Vs[t * KV_STRIDE + d] = qkv[row + 2 * EMBED];
    }
    __syncthreads();

    const int w = tid >> 5, lane = tid & 31;

    for (int q = w; q < SEQ; q += 8) {
        size_t qrow = (size_t)(b * SEQ + q) * (3 * EMBED) + h * HDIM;
        Qs[w * HDIM + lane]      = qkv[qrow + lane];
        Qs[w * HDIM + lane + 32] = qkv[qrow + lane + 32];
        __syncwarp();

        const int nk = q + 1;
        const int nchunk = (nk + 31) >> 5;
        float s_loc[9];
        #pragma unroll
        for (int j = 0; j < 9; j++) s_loc[j] = -1e30f;

        const float* qp = Qs + w * HDIM;
        #pragma unroll 1
        for (int j = 0; j < nchunk; j++) {
            int key = j * 32 + lane;
            if (key < nk) {
                const float* kp = Ks + key * KV_STRIDE;
                float s = 0.f;
                #pragma unroll
                for (int d = 0; d < 64; d++) s = fmaf(qp[d], kp[d], s);
                s_loc[j] = s * 0.125f;
            }
        }

        // row max
        float m = -1e30f;
        #pragma unroll
        for (int j = 0; j < 9; j++) if (j < nchunk) m = fmaxf(m, s_loc[j]);
        #pragma unroll
        for (int o = 16; o; o >>= 1) m = fmaxf(m, __shfl_xor_sync(0xffffffffu, m, o));

        // exp + sum
        float l = 0.f;
        #pragma unroll
        for (int j = 0; j < 9; j++) {
            if (j < nchunk) {
                s_loc[j] = __expf(s_loc[j] - m);   // invalid slots: exp(-huge)=0
                l += s_loc[j];
            }
        }
        #pragma unroll
        for (int o = 16; o; o >>= 1) l += __shfl_xor_sync(0xffffffffu, l, o);
        float inv = 1.f / l;

        // weighted V accumulation; lane owns dims (lane, lane+32)
        float o0 = 0.f, o1 = 0.f;
        #pragma unroll 1
        for (int j = 0; j < nchunk; j++) {
            float sj = s_loc[j];
            int kbase = j * 32;
            int cnt = nk - kbase; if (cnt > 32) cnt = 32;
            for (int src = 0; src < cnt; src++) {
                float p = __shfl_sync(0xffffffffu, sj, src);
                const float* vp = Vs + (kbase + src) * KV_STRIDE;
                o0 = fmaf(p, vp[lane],      o0);
                o1 = fmaf(p, vp[lane + 32], o1);
            }
        }
        size_t orow = (size_t)(b * SEQ + q) * EMBED + h * HDIM;
        out[orow + lane]      = o0 * inv;
        out[orow + lane + 32] = o1 * inv;
        __syncwarp();
    }
}

// ---------------- SiLU(u) * v -> u ----------------
__global__ void silu_mul_kernel(float* __restrict__ u, const float* __restrict__ v, int n4) {
    int idx = blockIdx.x * blockDim.x + threadIdx.x;
    if (idx >= n4) return;
    float4 uu = ((float4*)u)[idx];
    float4 vv = ((const float4*)v)[idx];
    uu.x = uu.x / (1.f + __expf(-uu.x)) * vv.x;
    uu.y = uu.y / (1.f + __expf(-uu.y)) * vv.y;
    uu.z = uu.z / (1.f + __expf(-uu.z)) * vv.z;
    uu.w = uu.w / (1.f + __expf(-uu.w)) * vv.w;
    ((float4*)u)[idx] = uu;
}

// ---------------- host orchestration ----------------
static inline dim3 gemm_grid(int M, int N) {
    return dim3((N + 127) / 128, (M + 127) / 128);
}

extern "C" void kernel_launch(void* const* d_in, const int* in_sizes, int n_in,
                              void* d_out, int out_size) {
    const float* x        = (const float*)d_in[0];   // (32,256,768)
    const float* cond     = (const float*)d_in[1];   // (32,1024)
    const float* patch_w  = (const float*)d_in[2];   // (768,1024)
    const float* patch_b  = (const float*)d_in[3];   // (1024)
    const float* ln_g     = (const float*)d_in[4];
    const float* ln_b     = (const float*)d_in[5];
    const float* pos      = (const float*)d_in[6];   // (1,257,1024)
    const float* cond_w   = (const float*)d_in[7];   // (1024,1024)
    const float* cond_b   = (const float*)d_in[8];
    const float* wqkv     = (const float*)d_in[9];   // (12,1024,3072)
    const float* wo       = (const float*)d_in[10];  // (12,1024,1024)
    const float* w1       = (const float*)d_in[11];  // (12,1024,2816)
    const float* w2       = (const float*)d_in[12];  // (12,2816,1024)
    const float* w3       = (const float*)d_in[13];  // (12,1024,2816)
    const float* anw      = (const float*)d_in[14];  // (12,1024)
    const float* fnw      = (const float*)d_in[15];  // (12,1024)

    float *h, *a, *qkv, *ao, *u, *v; float2* fc;
    cudaGetSymbolAddress((void**)&h,   g_h);
    cudaGetSymbolAddress((void**)&a,   g_a);
    cudaGetSymbolAddress((void**)&qkv, g_qkv);
    cudaGetSymbolAddress((void**)&ao,  g_ao);
    cudaGetSymbolAddress((void**)&u,   g_u);
    cudaGetSymbolAddress((void**)&v,   g_v);
    cudaGetSymbolAddress((void**)&fc,  g_fc);

    cudaFuncSetAttribute(attn_kernel, cudaFuncAttributeMaxDynamicSharedMemorySize, ATTN_SMEM);

    // RoPE table
    fc_kernel<<<(SEQ * 32 + 255) / 256, 256>>>(fc);

    // prelude: patch & cond embeds (into scratch), assemble + layernorm
    sgemm<false><<<gemm_grid(PTOK, EMBED), 256>>>(x, patch_w, qkv /*tmpA*/, PTOK, EMBED, 768);
    sgemm<false><<<gemm_grid(BATCH, EMBED), 256>>>(cond, cond_w, ao /*tmpC*/, BATCH, EMBED, EMBED);
    assemble_ln<<<TOK, 256>>>(qkv, ao, patch_b, cond_b, pos, ln_g, ln_b, h);

    for (int l = 0; l < NB; l++) {
        const float* wqkv_l = wqkv + (size_t)l * EMBED * 3 * EMBED;
        const float* wo_l   = wo   + (size_t)l * EMBED * EMBED;
        const float* w1_l   = w1   + (size_t)l * EMBED * HID;
        const float* w2_l   = w2   + (size_t)l * HID * EMBED;
        const float* w3_l   = w3   + (size_t)l * EMBED * HID;

        rmsnorm_kernel<<<TOK, 256>>>(h, anw + (size_t)l * EMBED, a);
        sgemm<false><<<gemm_grid(TOK, 3 * EMBED), 256>>>(a, wqkv_l, qkv, TOK, 3 * EMBED, EMBED);
        rope_kernel<<<(TOK * 512 + 255) / 256, 256>>>(qkv, fc);
        attn_kernel<<<dim3(HEADS, BATCH), 256, ATTN_SMEM>>>(qkv, ao);
        sgemm<true><<<gemm_grid(TOK, EMBED), 256>>>(ao, wo_l, h, TOK, EMBED, EMBED);

        rmsnorm_kernel<<<TOK, 256>>>(h, fnw + (size_t)l * EMBED, a);
        sgemm<false><<<gemm_grid(TOK, HID), 256>>>(a, w1_l, u, TOK, HID, EMBED);
        sgemm<false><<<gemm_grid(TOK, HID), 256>>>(a, w3_l, v, TOK, HID, EMBED);
        silu_mul_kernel<<<(TOK * HID / 4 + 255) / 256, 256>>>(u, v, TOK * HID / 4);
        sgemm<true><<<gemm_grid(TOK, EMBED), 256>>>(u, w2_l, h, TOK, EMBED, HID);
    }

    cudaMemcpyAsync(d_out, h, (size_t)TOK * EMBED * sizeof(float),
                    cudaMemcpyDeviceToDevice);
}

// round 4
// speedup vs baseline: 2.0285x; 2.0285x over previous
#include <cuda_runtime.h>
#include <cuda_bf16.h>
#include <math.h>

// ---------------- model dims ----------------
#define BATCH 32
#define SEQ   257
#define EMBED 1024
#define HEADS 16
#define HDIM  64
#define NB    12
#define HID   2816
#define TOK   (BATCH*SEQ)  // 8224
#define PTOK  (BATCH*256)  // 8192

// ---------------- scratch (device globals; no allocation allowed) ----------------
__device__ float  g_h  [TOK * EMBED];
__device__ float  g_a  [TOK * EMBED];
__device__ float  g_qkv[TOK * 3 * EMBED];
__device__ float  g_ao [TOK * EMBED];
__device__ float  g_u  [TOK * HID];
__device__ float  g_v  [TOK * HID];
__device__ float2 g_fc [SEQ * 32];
__device__ float  g_w  [156000000];   // rounded-to-tf32 weights (624 MB)

// offsets into g_w (floats)
#define OFF_PATCH 0
#define OFF_COND  786432
#define OFF_QKV   1835008
#define OFF_WO    39583744
#define OFF_W1    52166656
#define OFF_W2    86769664
#define OFF_W3    121372672

// ---------------- tf32 helpers ----------------
__device__ __forceinline__ float tf32r(float x) {
    unsigned u;
    asm("cvt.rna.tf32.f32 %0, %1;" : "=r"(u) : "f"(x));
    return __uint_as_float(u);
}

__global__ void round_tf32_kernel(const float* __restrict__ in, float* __restrict__ out, int n4) {
    int i = blockIdx.x * blockDim.x + threadIdx.x;
    if (i >= n4) return;
    float4 v = ((const float4*)in)[i];
    v.x = tf32r(v.x); v.y = tf32r(v.y); v.z = tf32r(v.z); v.w = tf32r(v.w);
    ((float4*)out)[i] = v;
}

// ---------------- cp.async helpers ----------------
__device__ __forceinline__ void cp_async16(float* smem, const float* gmem, bool pred) {
    unsigned s = (unsigned)__cvta_generic_to_shared(smem);
    if (pred)
        asm volatile("cp.async.cg.shared.global [%0], [%1], 16;\n" :: "r"(s), "l"(gmem));
}
__device__ __forceinline__ void cp_commit() { asm volatile("cp.async.commit_group;\n" ::); }
template<int N>
__device__ __forceinline__ void cp_wait() { asm volatile("cp.async.wait_group %0;\n" :: "n"(N)); }

__device__ __forceinline__ void mma_tf32(float* c, const unsigned* a, const unsigned* b) {
    asm volatile(
        "mma.sync.aligned.m16n8k8.row.col.f32.tf32.tf32.f32 "
        "{%0,%1,%2,%3}, {%4,%5,%6,%7}, {%8,%9}, {%0,%1,%2,%3};"
        : "+f"(c[0]), "+f"(c[1]), "+f"(c[2]), "+f"(c[3])
        : "r"(a[0]), "r"(a[1]), "r"(a[2]), "r"(a[3]), "r"(b[0]), "r"(b[1]));
}

// ---------------- TF32 tensor-core GEMM ----------------
// C[M,N] = A[M,K] @ B[K,N] (+C if ACC). A,B must hold tf32-rounded fp32 values.
// 128x128x32 tile, 256 threads (8 warps, 2x4), 64x32 per warp, m16n8k8 mma.
#define BM 128
#define BN 128
#define BK 32
#define LDA 36      // As[BM][LDA]  (row = m, 32 k-floats + pad)
#define LDB 136     // Bs[BK][LDB]  (row = k, 128 n-floats + pad)
#define A_STAGE (BM*LDA)   // 4608
#define B_STAGE (BK*LDB)   // 4352
#define GEMM_SMEM (2*(A_STAGE+B_STAGE)*4)  // 71680 B

template<bool ACC>
__global__ __launch_bounds__(256)
void tgemm(const float* __restrict__ A, const float* __restrict__ B,
           float* __restrict__ C, int M, int N, int K) {
    extern __shared__ float sm[];
    float* Asb[2] = { sm, sm + A_STAGE };
    float* Bsb[2] = { sm + 2 * A_STAGE, sm + 2 * A_STAGE + B_STAGE };

    const int tid = threadIdx.x;
    const int bm = blockIdx.y * BM;
    const int bn = blockIdx.x * BN;
    const int warp = tid >> 5, lane = tid & 31;
    const int wm = warp & 1, wn = warp >> 1;       // 2 x 4 warp grid
    const int gid = lane >> 2, tig = lane & 3;

    // gmem load mapping
    const int a_row = tid >> 1;                    // 0..127
    const int a_off = (tid & 1) * 16;              // half-row of 16 floats
    const bool a_ok = (bm + a_row) < M;
    const int b_row = tid >> 3;                    // 0..31
    const int b_off = (tid & 7) * 4;

    float acc[4][4][4];
    #pragma unroll
    for (int i = 0; i < 4; i++)
        #pragma unroll
        for (int j = 0; j < 4; j++)
            #pragma unroll
            for (int r = 0; r < 4; r++) acc[i][j][r] = 0.f;

    const int nk = K / BK;

    // stage loader
    #define LOAD_STAGE(kt, buf) do {                                            \
        const float* Ag = A + (size_t)(bm + a_row) * K + (kt) * BK + a_off;     \
        float* Asp = Asb[buf] + a_row * LDA + a_off;                            \
        _Pragma("unroll")                                                       \
        for (int i = 0; i < 4; i++) cp_async16(Asp + i * 4, Ag + i * 4, a_ok);  \
        const float* Bg = B + (size_t)((kt) * BK + b_row) * N + bn + b_off;     \
        float* Bsp = Bsb[buf] + b_row * LDB + b_off;                            \
        _Pragma("unroll")                                                       \
        for (int i = 0; i < 4; i++) cp_async16(Bsp + i * 32, Bg + i * 32, true);\
    } while (0)

    LOAD_STAGE(0, 0);
    cp_commit();

    for (int kt = 0; kt < nk; kt++) {
        const int cur = kt & 1;
        if (kt + 1 < nk) {
            LOAD_STAGE(kt + 1, 1 - cur);
            cp_commit();
            cp_wait<1>();
        } else {
            cp_wait<0>();
        }
        __syncthreads();

        const float* Ab = Asb[cur];
        const float* Bb = Bsb[cur];
        #pragma unroll
        for (int k0 = 0; k0 < BK; k0 += 8) {
            unsigned af[4][4], bf[4][2];
            #pragma unroll
            for (int mt = 0; mt < 4; mt++) {
                int m = wm * 64 + mt * 16 + gid;
                af[mt][0] = __float_as_uint(Ab[m * LDA + k0 + tig]);
                af[mt][1] = __float_as_uint(Ab[(m + 8) * LDA + k0 + tig]);
                af[mt][2] = __float_as_uint(Ab[m * LDA + k0 + tig + 4]);
                af[mt][3] = __float_as_uint(Ab[(m + 8) * LDA + k0 + tig + 4]);
            }
            #pragma unroll
            for (int nt = 0; nt < 4; nt++) {
                int n = wn * 32 + nt * 8 + gid;
                bf[nt][0] = __float_as_uint(Bb[(k0 + tig) * LDB + n]);
                bf[nt][1] = __float_as_uint(Bb[(k0 + tig + 4) * LDB + n]);
            }
            #pragma unroll
            for (int mt = 0; mt < 4; mt++)
                #pragma unroll
                for (int nt = 0; nt < 4; nt++)
                    mma_tf32(acc[mt][nt], af[mt], bf[nt]);
        }
        __syncthreads();
    }

    // epilogue
    #pragma unroll
    for (int mt = 0; mt < 4; mt++) {
        #pragma unroll
        for (int nt = 0; nt < 4; nt++) {
            const float* c = acc[mt][nt];
            int mg = bm + wm * 64 + mt * 16 + gid;
            int ng = bn + wn * 32 + nt * 8 + 2 * tig;
            if (mg < M) {
                float2* p = (float2*)(C + (size_t)mg * N + ng);
                if (ACC) { float2 t = *p; t.x += c[0]; t.y += c[1]; *p = t; }
                else     { *p = make_float2(c[0], c[1]); }
            }
            if (mg + 8 < M) {
                float2* p = (float2*)(C + (size_t)(mg + 8) * N + ng);
                if (ACC) { float2 t = *p; t.x += c[2]; t.y += c[3]; *p = t; }
                else     { *p = make_float2(c[2], c[3]); }
            }
        }
    }
}

// ---------------- block reduce ----------------
__device__ __forceinline__ float block_reduce_sum(float v, float* red) {
    int tid = threadIdx.x;
    #pragma unroll
    for (int o = 16; o; o >>= 1) v += __shfl_xor_sync(0xffffffffu, v, o);
    if ((tid & 31) == 0) red[tid >> 5] = v;
    __syncthreads();
    if (tid < 8) {
        float w = red[tid];
        #pragma unroll
        for (int o = 4; o; o >>= 1) w += __shfl_xor_sync(0xffu, w, o);
        if (tid == 0) red[0] = w;
    }
    __syncthreads();
    float r = red[0];
    __syncthreads();
    return r;
}

// ---------------- freqs_cis table ----------------
__global__ void fc_kernel(float2* __restrict__ fc) {
    int idx = blockIdx.x * blockDim.x + threadIdx.x;
    if (idx >= SEQ * 32) return;
    int s = idx / 32, i = idx % 32;
    if (s == 0) { fc[idx] = make_float2(0.f, 0.f); return; }
    int sp = s - 1;
    int gy = sp / 16, gx = sp % 16;
    int j   = (i < 16) ? i  : i - 16;
    int pos = (i < 16) ? gy : gx;
    float fr  = powf(10000.f, -(float)j / 16.f);
    float ang = (float)pos * fr;
    fc[idx] = make_float2(cosf(ang), sinf(ang));
}

// ---------------- assemble (patch+cond+pos) then LayerNorm ----------------
__global__ __launch_bounds__(256)
void assemble_ln(const float* __restrict__ tmpA, const float* __restrict__ tmpC,
                 const float* __restrict__ patch_b, const float* __restrict__ cond_b,
                 const float* __restrict__ pos, const float* __restrict__ g,
                 const float* __restrict__ bb, float* __restrict__ h) {
    __shared__ float red[8];
    int t = blockIdx.x;
    int b = t / SEQ, s = t % SEQ;
    int tid = threadIdx.x;
    float4 v;
    if (s == 0) {
        v = *((const float4*)(tmpC + (size_t)b * EMBED) + tid);
        float4 cb = ((const float4*)cond_b)[tid];
        v.x += cb.x; v.y += cb.y; v.z += cb.z; v.w += cb.w;
    } else {
        v = *((const float4*)(tmpA + (size_t)(b * 256 + s - 1) * EMBED) + tid);
        float4 pb = ((const float4*)patch_b)[tid];
        v.x += pb.x; v.y += pb.y; v.z += pb.z; v.w += pb.w;
    }
    float4 pe = *((const float4*)(pos + (size_t)s * EMBED) + tid);
    v.x += pe.x; v.y += pe.y; v.z += pe.z; v.w += pe.w;

    float sum  = block_reduce_sum(v.x + v.y + v.z + v.w, red);
    float mean = sum * (1.f / EMBED);
    float dx = v.x - mean, dy = v.y - mean, dz = v.z - mean, dw = v.w - mean;
    float ss  = block_reduce_sum(dx * dx + dy * dy + dz * dz + dw * dw, red);
    float r   = rsqrtf(ss * (1.f / EMBED) + 1e-6f);
    float4 gv = ((const float4*)g)[tid];
    float4 bv = ((const float4*)bb)[tid];
    float4 o  = make_float4(dx * r * gv.x + bv.x, dy * r * gv.y + bv.y,
                            dz * r * gv.z + bv.z, dw * r * gv.w + bv.w);
    *((float4*)(h + (size_t)t * EMBED) + tid) = o;
}

// ---------------- RMSNorm (emits tf32-rounded values for GEMM) ----------------
__global__ __launch_bounds__(256)
void rmsnorm_kernel(const float* __restrict__ h, const float* __restrict__ w,
                    float* __restrict__ out) {
    __shared__ float red[8];
    int t = blockIdx.x, tid = threadIdx.x;
    float4 v = *((const float4*)(h + (size_t)t * EMBED) + tid);
    float ss = block_reduce_sum(v.x * v.x + v.y * v.y + v.z * v.z + v.w * v.w, red);
    float r  = rsqrtf(ss * (1.f / EMBED) + 1e-5f);
    float4 wv = ((const float4*)w)[tid];
    float4 o  = make_float4(tf32r(v.x * r * wv.x), tf32r(v.y * r * wv.y),
                            tf32r(v.z * r * wv.z), tf32r(v.w * r * wv.w));
    *((float4*)(out + (size_t)t * EMBED) + tid) = o;
}

// ---------------- RoPE applied in-place to q,k parts of qkv ----------------
__global__ void rope_kernel(float* __restrict__ qkv, const float2* __restrict__ fc) {
    int idx = blockIdx.x * blockDim.x + threadIdx.x;
    if (idx >= TOK * 512) return;
    int t = idx >> 9;
    int r = idx & 511;
    int head = r >> 5, pair = r & 31;
    int s = t % SEQ;
    float2 cs = fc[s * 32 + pair];
    size_t base = (size_t)t * (3 * EMBED) + head * HDIM + pair * 2;
    float2* qp = (float2*)(qkv + base);
    float2 xv = *qp;
    *qp = make_float2(xv.x * cs.x - xv.y * cs.y, xv.y * cs.x + xv.x * cs.y);
    float2* kp = (float2*)(qkv + base + EMBED);
    xv = *kp;
    *kp = make_float2(xv.x * cs.x - xv.y * cs.y, xv.y * cs.x + xv.x * cs.y);
}

// ---------------- attention: one CTA per (b,h), K/V resident in smem ----------------
#define KV_STRIDE 65
#define ATTN_SMEM ((2 * SEQ * KV_STRIDE + 8 * HDIM) * 4)

__global__ __launch_bounds__(256)
void attn_kernel(const float* __restrict__ qkv, float* __restrict__ out) {
    extern __shared__ float smv[];
    float* Ks = smv;
    float* Vs = smv + SEQ * KV_STRIDE;
    float* Qs = Vs + SEQ * KV_STRIDE;

    const int h = blockIdx.x;
    const int b = blockIdx.y;
    const int tid = threadIdx.x;

    for (int i = tid; i < SEQ * HDIM; i += 256) {
        int t = i >> 6, d = i & 63;
        size_t row = (size_t)(b * SEQ + t) * (3 * EMBED) + h * HDIM + d;
        Ks[t * KV_STRIDE + d] = qkv[row + EMBED];
        Vs[t * KV_STRIDE + d] = qkv[row + 2 * EMBED];
    }
    __syncthreads();

    const int w = tid >> 5, lane = tid & 31;

    for (int q = w; q < SEQ; q += 8) {
        size_t qrow = (size_t)(b * SEQ + q) * (3 * EMBED) + h * HDIM;
        Qs[w * HDIM + lane]      = qkv[qrow + lane];
        Qs[w * HDIM + lane + 32] = qkv[qrow + lane + 32];
        __syncwarp();

        const int nk = q + 1;
        const int nchunk = (nk + 31) >> 5;
        float s_loc[9];
        #pragma unroll
        for (int j = 0; j < 9; j++) s_loc[j] = -1e30f;

        const float* qp = Qs + w * HDIM;
        #pragma unroll 1
        for (int j = 0; j < nchunk; j++) {
            int key = j * 32 + lane;
            if (key < nk) {
                const float* kp = Ks + key * KV_STRIDE;
                float s = 0.f;
                #pragma unroll
                for (int d = 0; d < 64; d++) s = fmaf(qp[d], kp[d], s);
                s_loc[j] = s * 0.125f;
            }
        }

        float m = -1e30f;
        #pragma unroll
        for (int j = 0; j < 9; j++) if (j < nchunk) m = fmaxf(m, s_loc[j]);
        #pragma unroll
        for (int o = 16; o; o >>= 1) m = fmaxf(m, __shfl_xor_sync(0xffffffffu, m, o));

        float l = 0.f;
        #pragma unroll
        for (int j = 0; j < 9; j++) {
            if (j < nchunk) {
                s_loc[j] = __expf(s_loc[j] - m);
                l += s_loc[j];
            }
        }
        #pragma unroll
        for (int o = 16; o; o >>= 1) l += __shfl_xor_sync(0xffffffffu, l, o);
        float inv = 1.f / l;

        float o0 = 0.f, o1 = 0.f;
        #pragma unroll 1
        for (int j = 0; j < nchunk; j++) {
            float sj = s_loc[j];
            int kbase = j * 32;
            int cnt = nk - kbase; if (cnt > 32) cnt = 32;
            for (int src = 0; src < cnt; src++) {
                float p = __shfl_sync(0xffffffffu, sj, src);
                const float* vp = Vs + (kbase + src) * KV_STRIDE;
                o0 = fmaf(p, vp[lane],      o0);
                o1 = fmaf(p, vp[lane + 32], o1);
            }
        }
        size_t orow = (size_t)(b * SEQ + q) * EMBED + h * HDIM;
        out[orow + lane]      = tf32r(o0 * inv);
        out[orow + lane + 32] = tf32r(o1 * inv);
        __syncwarp();
    }
}

// ---------------- SiLU(u) * v -> u (tf32-rounded) ----------------
__global__ void silu_mul_kernel(float* __restrict__ u, const float* __restrict__ v, int n4) {
    int idx = blockIdx.x * blockDim.x + threadIdx.x;
    if (idx >= n4) return;
    float4 uu = ((float4*)u)[idx];
    float4 vv = ((const float4*)v)[idx];
    uu.x = tf32r(uu.x / (1.f + __expf(-uu.x)) * vv.x);
    uu.y = tf32r(uu.y / (1.f + __expf(-uu.y)) * vv.y);
    uu.z = tf32r(uu.z / (1.f + __expf(-uu.z)) * vv.z);
    uu.w = tf32r(uu.w / (1.f + __expf(-uu.w)) * vv.w);
    ((float4*)u)[idx] = uu;
}

// ---------------- host orchestration ----------------
static inline dim3 gemm_grid(int M, int N) {
    return dim3((N + BN - 1) / BN, (M + BM - 1) / BM);
}
static inline void round_w(const float* in, float* out, size_t n) {
    int n4 = (int)(n / 4);
    round_tf32_kernel<<<(n4 + 255) / 256, 256>>>(in, out, n4);
}

extern "C" void kernel_launch(void* const* d_in, const int* in_sizes, int n_in,
                              void* d_out, int out_size) {
    const float* x        = (const float*)d_in[0];
    const float* cond     = (const float*)d_in[1];
    const float* patch_w  = (const float*)d_in[2];
    const float* patch_b  = (const float*)d_in[3];
    const float* ln_g     = (const float*)d_in[4];
    const float* ln_b     = (const float*)d_in[5];
    const float* pos      = (const float*)d_in[6];
    const float* cond_w   = (const float*)d_in[7];
    const float* cond_b   = (const float*)d_in[8];
    const float* wqkv     = (const float*)d_in[9];
    const float* wo       = (const float*)d_in[10];
    const float* w1       = (const float*)d_in[11];
    const float* w2       = (const float*)d_in[12];
    const float* w3       = (const float*)d_in[13];
    const float* anw      = (const float*)d_in[14];
    const float* fnw      = (const float*)d_in[15];

    float *h, *a, *qkv, *ao, *u, *v, *w; float2* fc;
    cudaGetSymbolAddress((void**)&h,   g_h);
    cudaGetSymbolAddress((void**)&a,   g_a);
    cudaGetSymbolAddress((void**)&qkv, g_qkv);
    cudaGetSymbolAddress((void**)&ao,  g_ao);
    cudaGetSymbolAddress((void**)&u,   g_u);
    cudaGetSymbolAddress((void**)&v,   g_v);
    cudaGetSymbolAddress((void**)&w,   g_w);
    cudaGetSymbolAddress((void**)&fc,  g_fc);

    cudaFuncSetAttribute(attn_kernel, cudaFuncAttributeMaxDynamicSharedMemorySize, ATTN_SMEM);
    cudaFuncSetAttribute(tgemm<false>, cudaFuncAttributeMaxDynamicSharedMemorySize, GEMM_SMEM);
    cudaFuncSetAttribute(tgemm<true>,  cudaFuncAttributeMaxDynamicSharedMemorySize, GEMM_SMEM);

    // round weights + inputs to tf32-exact fp32 (every launch; deterministic)
    round_w(patch_w, w + OFF_PATCH, (size_t)768 * EMBED);
    round_w(cond_w,  w + OFF_COND,  (size_t)EMBED * EMBED);
    round_w(wqkv,    w + OFF_QKV,   (size_t)NB * EMBED * 3 * EMBED);
    round_w(wo,      w + OFF_WO,    (size_t)NB * EMBED * EMBED);
    round_w(w1,      w + OFF_W1,    (size_t)NB * EMBED * HID);
    round_w(w2,      w + OFF_W2,    (size_t)NB * HID * EMBED);
    round_w(w3,      w + OFF_W3,    (size_t)NB * EMBED * HID);
    round_w(x,       u,             (size_t)PTOK * 768);       // rounded x -> g_u
    round_w(cond,    v,             (size_t)BATCH * EMBED);    // rounded cond -> g_v

    fc_kernel<<<(SEQ * 32 + 255) / 256, 256>>>(fc);

    // prelude
    tgemm<false><<<gemm_grid(PTOK, EMBED), 256, GEMM_SMEM>>>(u, w + OFF_PATCH, qkv, PTOK, EMBED, 768);
    tgemm<false><<<gemm_grid(BATCH, EMBED), 256, GEMM_SMEM>>>(v, w + OFF_COND, ao, BATCH, EMBED, EMBED);
    assemble_ln<<<TOK, 256>>>(qkv, ao, patch_b, cond_b, pos, ln_g, ln_b, h);

    for (int l = 0; l < NB; l++) {
        const float* wqkv_l = w + OFF_QKV + (size_t)l * EMBED * 3 * EMBED;
        const float* wo_l   = w + OFF_WO  + (size_t)l * EMBED * EMBED;
        const float* w1_l   = w + OFF_W1  + (size_t)l * EMBED * HID;
        const float* w2_l   = w + OFF_W2  + (size_t)l * HID * EMBED;
        const float* w3_l   = w + OFF_W3  + (size_t)l * EMBED * HID;

        rmsnorm_kernel<<<TOK, 256>>>(h, anw + (size_t)l * EMBED, a);
        tgemm<false><<<gemm_grid(TOK, 3 * EMBED), 256, GEMM_SMEM>>>(a, wqkv_l, qkv, TOK, 3 * EMBED, EMBED);
        rope_kernel<<<(TOK * 512 + 255) / 256, 256>>>(qkv, fc);
        attn_kernel<<<dim3(HEADS, BATCH), 256, ATTN_SMEM>>>(qkv, ao);
        tgemm<true><<<gemm_grid(TOK, EMBED), 256, GEMM_SMEM>>>(ao, wo_l, h, TOK, EMBED, EMBED);

        rmsnorm_kernel<<<TOK, 256>>>(h, fnw + (size_t)l * EMBED, a);
        tgemm<false><<<gemm_grid(TOK, HID), 256, GEMM_SMEM>>>(a, w1_l, u, TOK, HID, EMBED);
        tgemm<false><<<gemm_grid(TOK, HID), 256, GEMM_SMEM>>>(a, w3_l, v, TOK, HID, EMBED);
        silu_mul_kernel<<<(TOK * HID / 4 + 255) / 256, 256>>>(u, v, TOK * HID / 4);
        tgemm<true><<<gemm_grid(TOK, EMBED), 256, GEMM_SMEM>>>(u, w2_l, h, TOK, EMBED, HID);
    }

    cudaMemcpyAsync(d_out, h, (size_t)TOK * EMBED * sizeof(float),
                    cudaMemcpyDeviceToDevice);
}

// round 6
// speedup vs baseline: 2.0597x; 1.0154x over previous
#include <cuda_runtime.h>
#include <cuda_bf16.h>
#include <math.h>
#include <stdint.h>

// ---------------- model dims ----------------
#define BATCH 32
#define SEQ   257
#define EMBED 1024
#define HEADS 16
#define HDIM  64
#define NB    12
#define HID   2816
#define TOK   (BATCH*SEQ)  // 8224
#define PTOK  (BATCH*256)  // 8192

// ---------------- scratch ----------------
__device__ float  g_h  [TOK * EMBED];
__device__ float  g_a  [TOK * EMBED];
__device__ float  g_qkv[TOK * 3 * EMBED];
__device__ float  g_ao [TOK * EMBED];
__device__ float  g_u  [TOK * HID];
__device__ float  g_v  [TOK * HID];
__device__ float2 g_fc [SEQ * 32];
__device__ float  g_w  [156000000];   // transposed + tf32-rounded weights

#define OFF_PATCH 0
#define OFF_COND  786432
#define OFF_QKV   1835008
#define OFF_WO    39583744
#define OFF_W1    52166656
#define OFF_W2    86769664
#define OFF_W3    121372672

// ---------------- helpers ----------------
__device__ __forceinline__ float tf32r(float x) {
    unsigned u;
    asm("cvt.rna.tf32.f32 %0, %1;" : "=r"(u) : "f"(x));
    return __uint_as_float(u);
}
__device__ __forceinline__ void cp_async16(float* smem, const float* gmem, bool pred) {
    unsigned s = (unsigned)__cvta_generic_to_shared(smem);
    if (pred)
        asm volatile("cp.async.cg.shared.global [%0], [%1], 16;" :: "r"(s), "l"(gmem));
}
__device__ __forceinline__ void cp_commit() { asm volatile("cp.async.commit_group;" ::); }
template<int N>
__device__ __forceinline__ void cp_wait() { asm volatile("cp.async.wait_group %0;" :: "n"(N)); }

__device__ __forceinline__ void mma_tf32(float* c, const unsigned* a, const unsigned* b) {
    asm volatile(
        "mma.sync.aligned.m16n8k8.row.col.f32.tf32.tf32.f32 "
        "{%0,%1,%2,%3}, {%4,%5,%6,%7}, {%8,%9}, {%0,%1,%2,%3};"
        : "+f"(c[0]), "+f"(c[1]), "+f"(c[2]), "+f"(c[3])
        : "r"(a[0]), "r"(a[1]), "r"(a[2]), "r"(a[3]), "r"(b[0]), "r"(b[1]));
}

// ---------------- TF32 tensor-core GEMM v2 ----------------
// C[M,N] = A[M,K] @ BT[N,K]^T (+C if ACC). A,BT hold tf32-rounded fp32, K-major.
// CTA tile 128x256x32, 8 warps (2x4) of 64x64, 3-stage cp.async,
// register fragment double-buffering. N,K must be multiples of 256/32.
#define TBM 128
#define TBN 256
#define TBK 32
#define SLD 36                    // smem row stride (floats): 32 + 4 pad
#define SA_F (TBM * SLD)          // 4608 floats
#define SB_F (TBN * SLD)          // 9216 floats
#define STG_F (SA_F + SB_F)       // 13824 floats
#define TSMEM (3 * STG_F * 4)     // 165888 bytes

template<bool ACC>
__global__ __launch_bounds__(256, 1)
void tgemm(const float* __restrict__ A, const float* __restrict__ BT,
           float* __restrict__ C, int M, int N, int K) {
    extern __shared__ float sm[];

    const int tid = threadIdx.x;
    const int warp = tid >> 5, lane = tid & 31;
    const int wm = warp & 1, wn = warp >> 1;        // 2 x 4 warps of 64x64
    const int gid = lane >> 2, tig = lane & 3;
    const int bm = blockIdx.y * TBM, bn = blockIdx.x * TBN;

    // gmem->smem mapping
    const int a_row = tid >> 1;                     // 0..127
    const int a_half = (tid & 1) * 16;              // floats
    const bool a_ok = (bm + a_row) < M;
    const float* Ag = A + (size_t)(bm + a_row) * K + a_half;
    const float* Bg = BT + (size_t)(bn + tid) * K;  // tid = 0..255 -> n row

    float acc[4][8][4];
    #pragma unroll
    for (int i = 0; i < 4; i++)
        #pragma unroll
        for (int j = 0; j < 8; j++)
            #pragma unroll
            for (int r = 0; r < 4; r++) acc[i][j][r] = 0.f;

    const int nk = K / TBK;

    auto load_stage = [&](int kt, int s) {
        float* As = sm + s * STG_F;
        float* Bs = As + SA_F;
        const float* ag = Ag + kt * TBK;
        float* ad = As + a_row * SLD + a_half;
        #pragma unroll
        for (int c = 0; c < 4; c++) cp_async16(ad + c * 4, ag + c * 4, a_ok);
        const float* bg = Bg + kt * TBK;
        float* bd = Bs + tid * SLD;
        #pragma unroll
        for (int c = 0; c < 8; c++) cp_async16(bd + c * 4, bg + c * 4, true);
    };

    load_stage(0, 0); cp_commit();
    if (nk > 1) load_stage(1, 1);
    cp_commit();

    unsigned afr[2][16], bfr[2][16];

    #define LOAD_FRAGS(buf, k0) do {                                             \
        _Pragma("unroll")                                                        \
        for (int mt = 0; mt < 4; mt++) {                                         \
            const int m = wm * 64 + mt * 16 + gid;                               \
            afr[buf][mt*4+0] = __float_as_uint(Ab[m * SLD + (k0) + tig]);        \
            afr[buf][mt*4+1] = __float_as_uint(Ab[(m + 8) * SLD + (k0) + tig]);  \
            afr[buf][mt*4+2] = __float_as_uint(Ab[m * SLD + (k0) + tig + 4]);    \
            afr[buf][mt*4+3] = __float_as_uint(Ab[(m + 8) * SLD + (k0) + tig + 4]); \
        }                                                                        \
        _Pragma("unroll")                                                        \
        for (int nt = 0; nt < 8; nt++) {                                         \
            const int n = wn * 64 + nt * 8 + gid;                                \
            bfr[buf][nt*2+0] = __float_as_uint(Bb[n * SLD + (k0) + tig]);        \
            bfr[buf][nt*2+1] = __float_as_uint(Bb[n * SLD + (k0) + tig + 4]);    \
        }                                                                        \
    } while (0)

    for (int kt = 0; kt < nk; kt++) {
        const int s = kt % 3;
        cp_wait<1>();
        __syncthreads();
        if (kt + 2 < nk) load_stage(kt + 2, (kt + 2) % 3);
        cp_commit();

        const float* Ab = sm + s * STG_F;
        const float* Bb = Ab + SA_F;

        LOAD_FRAGS(0, 0);
        #pragma unroll
        for (int j = 0; j < 4; j++) {
            if (j < 3) {
                const int nb = (j + 1) & 1;
                LOAD_FRAGS(nb, (j + 1) * 8);
            }
            const int cb = j & 1;
            #pragma unroll
            for (int mt = 0; mt < 4; mt++)
                #pragma unroll
                for (int nt = 0; nt < 8; nt++)
                    mma_tf32(acc[mt][nt], &afr[cb][mt * 4], &bfr[cb][nt * 2]);
        }
    }
    #undef LOAD_FRAGS

    // epilogue
    #pragma unroll
    for (int mt = 0; mt < 4; mt++) {
        #pragma unroll
        for (int nt = 0; nt < 8; nt++) {
            const float* c = acc[mt][nt];
            const int mg = bm + wm * 64 + mt * 16 + gid;
            const int ng = bn + wn * 64 + nt * 8 + 2 * tig;
            if (mg < M) {
                float2* p = (float2*)(C + (size_t)mg * N + ng);
                if (ACC) { float2 t = *p; t.x += c[0]; t.y += c[1]; *p = t; }
                else     { *p = make_float2(c[0], c[1]); }
            }
            if (mg + 8 < M) {
                float2* p = (float2*)(C + (size_t)(mg + 8) * N + ng);
                if (ACC) { float2 t = *p; t.x += c[2]; t.y += c[3]; *p = t; }
                else     { *p = make_float2(c[2], c[3]); }
            }
        }
    }
}

// ---------------- weight prep: transpose + tf32 round ----------------
__global__ void wprep_kernel(const float* __restrict__ W, float* __restrict__ WT, int K, int N) {
    __shared__ float t[32][33];
    const size_t lo = (size_t)blockIdx.z * K * N;
    const float* Wp = W + lo;
    float* Tp = WT + lo;
    const int k0 = blockIdx.y * 32, n0 = blockIdx.x * 32;
    const int x = threadIdx.x, y = threadIdx.y;
    #pragma unroll
    for (int i = 0; i < 32; i += 8)
        t[y + i][x] = Wp[(size_t)(k0 + y + i) * N + (n0 + x)];
    __syncthreads();
    #pragma unroll
    for (int i = 0; i < 32; i += 8)
        Tp[(size_t)(n0 + y + i) * K + (k0 + x)] = tf32r(t[x][y + i]);
}

__global__ void round_tf32_kernel(const float* __restrict__ in, float* __restrict__ out, int n4) {
    int i = blockIdx.x * blockDim.x + threadIdx.x;
    if (i >= n4) return;
    float4 v = ((const float4*)in)[i];
    v.x = tf32r(v.x); v.y = tf32r(v.y); v.z = tf32r(v.z); v.w = tf32r(v.w);
    ((float4*)out)[i] = v;
}

// ---------------- block reduce ----------------
__device__ __forceinline__ float block_reduce_sum(float v, float* red) {
    int tid = threadIdx.x;
    #pragma unroll
    for (int o = 16; o; o >>= 1) v += __shfl_xor_sync(0xffffffffu, v, o);
    if ((tid & 31) == 0) red[tid >> 5] = v;
    __syncthreads();
    if (tid < 8) {
        float w = red[tid];
        #pragma unroll
        for (int o = 4; o; o >>= 1) w += __shfl_xor_sync(0xffu, w, o);
        if (tid == 0) red[0] = w;
    }
    __syncthreads();
    float r = red[0];
    __syncthreads();
    return r;
}

// ---------------- freqs_cis table ----------------
__global__ void fc_kernel(float2* __restrict__ fc) {
    int idx = blockIdx.x * blockDim.x + threadIdx.x;
    if (idx >= SEQ * 32) return;
    int s = idx / 32, i = idx % 32;
    if (s == 0) { fc[idx] = make_float2(0.f, 0.f); return; }
    int sp = s - 1;
    int gy = sp / 16, gx = sp % 16;
    int j   = (i < 16) ? i  : i - 16;
    int pos = (i < 16) ? gy : gx;
    float fr  = powf(10000.f, -(float)j / 16.f);
    float ang = (float)pos * fr;
    fc[idx] = make_float2(cosf(ang), sinf(ang));
}

// ---------------- assemble + LayerNorm ----------------
__global__ __launch_bounds__(256)
void assemble_ln(const float* __restrict__ tmpA, const float* __restrict__ tmpC,
                 const float* __restrict__ patch_b, const float* __restrict__ cond_b,
                 const float* __restrict__ pos, const float* __restrict__ g,
                 const float* __restrict__ bb, float* __restrict__ h) {
    __shared__ float red[8];
    int t = blockIdx.x;
    int b = t / SEQ, s = t % SEQ;
    int tid = threadIdx.x;
    float4 v;
    if (s == 0) {
        v = *((const float4*)(tmpC + (size_t)b * EMBED) + tid);
        float4 cb = ((const float4*)cond_b)[tid];
        v.x += cb.x; v.y += cb.y; v.z += cb.z; v.w += cb.w;
    } else {
        v = *((const float4*)(tmpA + (size_t)(b * 256 + s - 1) * EMBED) + tid);
        float4 pb = ((const float4*)patch_b)[tid];
        v.x += pb.x; v.y += pb.y; v.z += pb.z; v.w += pb.w;
    }
    float4 pe = *((const float4*)(pos + (size_t)s * EMBED) + tid);
    v.x += pe.x; v.y += pe.y; v.z += pe.z; v.w += pe.w;

    float sum  = block_reduce_sum(v.x + v.y + v.z + v.w, red);
    float mean = sum * (1.f / EMBED);
    float dx = v.x - mean, dy = v.y - mean, dz = v.z - mean, dw = v.w - mean;
    float ss  = block_reduce_sum(dx * dx + dy * dy + dz * dz + dw * dw, red);
    float r   = rsqrtf(ss * (1.f / EMBED) + 1e-6f);
    float4 gv = ((const float4*)g)[tid];
    float4 bv = ((const float4*)bb)[tid];
    float4 o  = make_float4(dx * r * gv.x + bv.x, dy * r * gv.y + bv.y,
                            dz * r * gv.z + bv.z, dw * r * gv.w + bv.w);
    *((float4*)(h + (size_t)t * EMBED) + tid) = o;
}

// ---------------- RMSNorm (tf32-rounded out) ----------------
__global__ __launch_bounds__(256)
void rmsnorm_kernel(const float* __restrict__ h, const float* __restrict__ w,
                    float* __restrict__ out) {
    __shared__ float red[8];
    int t = blockIdx.x, tid = threadIdx.x;
    float4 v = *((const float4*)(h + (size_t)t * EMBED) + tid);
    float ss = block_reduce_sum(v.x * v.x + v.y * v.y + v.z * v.z + v.w * v.w, red);
    float r  = rsqrtf(ss * (1.f / EMBED) + 1e-5f);
    float4 wv = ((const float4*)w)[tid];
    float4 o  = make_float4(tf32r(v.x * r * wv.x), tf32r(v.y * r * wv.y),
                            tf32r(v.z * r * wv.z), tf32r(v.w * r * wv.w));
    *((float4*)(out + (size_t)t * EMBED) + tid) = o;
}

// ---------------- RoPE ----------------
__global__ void rope_kernel(float* __restrict__ qkv, const float2* __restrict__ fc) {
    int idx = blockIdx.x * blockDim.x + threadIdx.x;
    if (idx >= TOK * 512) return;
    int t = idx >> 9;
    int r = idx & 511;
    int head = r >> 5, pair = r & 31;
    int s = t % SEQ;
    float2 cs = fc[s * 32 + pair];
    size_t base = (size_t)t * (3 * EMBED) + head * HDIM + pair * 2;
    float2* qp = (float2*)(qkv + base);
    float2 xv = *qp;
    *qp = make_float2(xv.x * cs.x - xv.y * cs.y, xv.y * cs.x + xv.x * cs.y);
    float2* kp = (float2*)(qkv + base + EMBED);
    xv = *kp;
    *kp = make_float2(xv.x * cs.x - xv.y * cs.y, xv.y * cs.x + xv.x * cs.y);
}

// ---------------- attention ----------------
#define KV_STRIDE 65
#define ATTN_SMEM ((2 * SEQ * KV_STRIDE + 8 * HDIM) * 4)

__global__ __launch_bounds__(256)
void attn_kernel(const float* __restrict__ qkv, float* __restrict__ out) {
    extern __shared__ float smv[];
    float* Ks = smv;
    float* Vs = smv + SEQ * KV_STRIDE;
    float* Qs = Vs + SEQ * KV_STRIDE;

    const int h = blockIdx.x;
    const int b = blockIdx.y;
    const int tid = threadIdx.x;

    for (int i = tid; i < SEQ * HDIM; i += 256) {
        int t = i >> 6, d = i & 63;
        size_t row = (size_t)(b * SEQ + t) * (3 * EMBED) + h * HDIM + d;
        Ks[t * KV_STRIDE + d] = qkv[row + EMBED];
        Vs[t * KV_STRIDE + d] = qkv[row + 2 * EMBED];
    }
    __syncthreads();

    const int w = tid >> 5, lane = tid & 31;

    for (int q = w; q < SEQ; q += 8) {
        size_t qrow = (size_t)(b * SEQ + q) * (3 * EMBED) + h * HDIM;
        Qs[w * HDIM + lane]      = qkv[qrow + lane];
        Qs[w * HDIM + lane + 32] = qkv[qrow + lane + 32];
        __syncwarp();

        const int nk = q + 1;
        const int nchunk = (nk + 31) >> 5;
        float s_loc[9];
        #pragma unroll
        for (int j = 0; j < 9; j++) s_loc[j] = -1e30f;

        const float* qp = Qs + w * HDIM;
        #pragma unroll 1
        for (int j = 0; j < nchunk; j++) {
            int key = j * 32 + lane;
            if (key < nk) {
                const float* kp = Ks + key * KV_STRIDE;
                float s = 0.f;
                #pragma unroll
                for (int d = 0; d < 64; d++) s = fmaf(qp[d], kp[d], s);
                s_loc[j] = s * 0.125f;
            }
        }

        float m = -1e30f;
        #pragma unroll
        for (int j = 0; j < 9; j++) if (j < nchunk) m = fmaxf(m, s_loc[j]);
        #pragma unroll
        for (int o = 16; o; o >>= 1) m = fmaxf(m, __shfl_xor_sync(0xffffffffu, m, o));

        float l = 0.f;
        #pragma unroll
        for (int j = 0; j < 9; j++) {
            if (j < nchunk) {
                s_loc[j] = __expf(s_loc[j] - m);
                l += s_loc[j];
            }
        }
        #pragma unroll
        for (int o = 16; o; o >>= 1) l += __shfl_xor_sync(0xffffffffu, l, o);
        float inv = 1.f / l;

        float o0 = 0.f, o1 = 0.f;
        #pragma unroll 1
        for (int j = 0; j < nchunk; j++) {
            float sj = s_loc[j];
            int kbase = j * 32;
            int cnt = nk - kbase; if (cnt > 32) cnt = 32;
            for (int src = 0; src < cnt; src++) {
                float p = __shfl_sync(0xffffffffu, sj, src);
                const float* vp = Vs + (kbase + src) * KV_STRIDE;
                o0 = fmaf(p, vp[lane],      o0);
                o1 = fmaf(p, vp[lane + 32], o1);
            }
        }
        size_t orow = (size_t)(b * SEQ + q) * EMBED + h * HDIM;
        out[orow + lane]      = tf32r(o0 * inv);
        out[orow + lane + 32] = tf32r(o1 * inv);
        __syncwarp();
    }
}

// ---------------- SiLU(u) * v -> u (tf32-rounded) ----------------
__global__ void silu_mul_kernel(float* __restrict__ u, const float* __restrict__ v, int n4) {
    int idx = blockIdx.x * blockDim.x + threadIdx.x;
    if (idx >= n4) return;
    float4 uu = ((float4*)u)[idx];
    float4 vv = ((const float4*)v)[idx];
    uu.x = tf32r(uu.x / (1.f + __expf(-uu.x)) * vv.x);
    uu.y = tf32r(uu.y / (1.f + __expf(-uu.y)) * vv.y);
    uu.z = tf32r(uu.z / (1.f + __expf(-uu.z)) * vv.z);
    uu.w = tf32r(uu.w / (1.f + __expf(-uu.w)) * vv.w);
    ((float4*)u)[idx] = uu;
}

// ---------------- host ----------------
static inline dim3 tc_grid(int M, int N) {
    return dim3(N / TBN, (M + TBM - 1) / TBM);
}

extern "C" void kernel_launch(void* const* d_in, const int* in_sizes, int n_in,
                              void* d_out, int out_size) {
    const float* x        = (const float*)d_in[0];
    const float* cond     = (const float*)d_in[1];
    const float* patch_w  = (const float*)d_in[2];
    const float* patch_b  = (const float*)d_in[3];
    const float* ln_g     = (const float*)d_in[4];
    const float* ln_b     = (const float*)d_in[5];
    const float* pos      = (const float*)d_in[6];
    const float* cond_w   = (const float*)d_in[7];
    const float* cond_b   = (const float*)d_in[8];
    const float* wqkv     = (const float*)d_in[9];
    const float* wo       = (const float*)d_in[10];
    const float* w1       = (const float*)d_in[11];
    const float* w2       = (const float*)d_in[12];
    const float* w3       = (const float*)d_in[13];
    const float* anw      = (const float*)d_in[14];
    const float* fnw      = (const float*)d_in[15];

    float *h, *a, *qkv, *ao, *u, *v, *w; float2* fc;
    cudaGetSymbolAddress((void**)&h,   g_h);
    cudaGetSymbolAddress((void**)&a,   g_a);
    cudaGetSymbolAddress((void**)&qkv, g_qkv);
    cudaGetSymbolAddress((void**)&ao,  g_ao);
    cudaGetSymbolAddress((void**)&u,   g_u);
    cudaGetSymbolAddress((void**)&v,   g_v);
    cudaGetSymbolAddress((void**)&w,   g_w);
    cudaGetSymbolAddress((void**)&fc,  g_fc);

    cudaFuncSetAttribute(attn_kernel,  cudaFuncAttributeMaxDynamicSharedMemorySize, ATTN_SMEM);
    cudaFuncSetAttribute(tgemm<false>, cudaFuncAttributeMaxDynamicSharedMemorySize, TSMEM);
    cudaFuncSetAttribute(tgemm<true>,  cudaFuncAttributeMaxDynamicSharedMemorySize, TSMEM);

    dim3 tb(32, 8);
    // weights: transpose [K,N] -> [N,K] + tf32 round
    wprep_kernel<<<dim3(1024/32, 768/32, 1),  tb>>>(patch_w, w + OFF_PATCH, 768, 1024);
    wprep_kernel<<<dim3(1024/32, 1024/32, 1), tb>>>(cond_w,  w + OFF_COND,  1024, 1024);
    wprep_kernel<<<dim3(3072/32, 1024/32, NB), tb>>>(wqkv,   w + OFF_QKV,   1024, 3072);
    wprep_kernel<<<dim3(1024/32, 1024/32, NB), tb>>>(wo,     w + OFF_WO,    1024, 1024);
    wprep_kernel<<<dim3(2816/32, 1024/32, NB), tb>>>(w1,     w + OFF_W1,    1024, 2816);
    wprep_kernel<<<dim3(1024/32, 2816/32, NB), tb>>>(w2,     w + OFF_W2,    2816, 1024);
    wprep_kernel<<<dim3(2816/32, 1024/32, NB), tb>>>(w3,     w + OFF_W3,    1024, 2816);
    // inputs: tf32 round
    round_tf32_kernel<<<(PTOK*768/4 + 255)/256, 256>>>(x, u, PTOK*768/4);
    round_tf32_kernel<<<(BATCH*EMBED/4 + 255)/256, 256>>>(cond, v, BATCH*EMBED/4);

    fc_kernel<<<(SEQ * 32 + 255) / 256, 256>>>(fc);

    // prelude
    tgemm<false><<<tc_grid(PTOK, EMBED), 256, TSMEM>>>(u, w + OFF_PATCH, qkv, PTOK, EMBED, 768);
    tgemm<false><<<tc_grid(BATCH, EMBED), 256, TSMEM>>>(v, w + OFF_COND, ao, BATCH, EMBED, EMBED);
    assemble_ln<<<TOK, 256>>>(qkv, ao, patch_b, cond_b, pos, ln_g, ln_b, h);

    for (int l = 0; l < NB; l++) {
        const float* wqkv_l = w + OFF_QKV + (size_t)l * EMBED * 3 * EMBED;
        const float* wo_l   = w + OFF_WO  + (size_t)l * EMBED * EMBED;
        const float* w1_l   = w + OFF_W1  + (size_t)l * EMBED * HID;
        const float* w2_l   = w + OFF_W2  + (size_t)l * HID * EMBED;
        const float* w3_l   = w + OFF_W3  + (size_t)l * EMBED * HID;

        rmsnorm_kernel<<<TOK, 256>>>(h, anw + (size_t)l * EMBED, a);
        tgemm<false><<<tc_grid(TOK, 3 * EMBED), 256, TSMEM>>>(a, wqkv_l, qkv, TOK, 3 * EMBED, EMBED);
        rope_kernel<<<(TOK * 512 + 255) / 256, 256>>>(qkv, fc);
        attn_kernel<<<dim3(HEADS, BATCH), 256, ATTN_SMEM>>>(qkv, ao);
        tgemm<true><<<tc_grid(TOK, EMBED), 256, TSMEM>>>(ao, wo_l, h, TOK, EMBED, EMBED);

        rmsnorm_kernel<<<TOK, 256>>>(h, fnw + (size_t)l * EMBED, a);
        tgemm<false><<<tc_grid(TOK, HID), 256, TSMEM>>>(a, w1_l, u, TOK, HID, EMBED);
        tgemm<false><<<tc_grid(TOK, HID), 256, TSMEM>>>(a, w3_l, v, TOK, HID, EMBED);
        silu_mul_kernel<<<(TOK * HID / 4 + 255) / 256, 256>>>(u, v, TOK * HID / 4);
        tgemm<true><<<tc_grid(TOK, EMBED), 256, TSMEM>>>(u, w2_l, h, TOK, EMBED, HID);
    }

    cudaMemcpyAsync(d_out, h, (size_t)TOK * EMBED * sizeof(float),
                    cudaMemcpyDeviceToDevice);
}

// round 7
// speedup vs baseline: 3.1199x; 1.5147x over previous
#include <cuda_runtime.h>
#include <cuda_fp16.h>
#include <math.h>
#include <stdint.h>

// ---------------- model dims ----------------
#define BATCH 32
#define SEQ   257
#define EMBED 1024
#define HEADS 16
#define HDIM  64
#define NB    12
#define HID   2816
#define TOK   (BATCH*SEQ)  // 8224
#define PTOK  (BATCH*256)  // 8192

// ---------------- scratch ----------------
__device__ float  g_h  [TOK * EMBED];
__device__ float  g_qkv[TOK * 3 * EMBED];
__device__ float  g_ct [BATCH * EMBED];      // cond tmp (float)
__device__ float  g_u  [TOK * HID];
__device__ float  g_v  [TOK * HID];
__device__ float2 g_fc [SEQ * 32];
__device__ __half g_wh [156000000];          // transposed fp16 weights (312 MB)
__device__ __half g_ah [TOK * EMBED];        // rmsnorm out (fp16)
__device__ __half g_aoh[TOK * EMBED];        // attn out (fp16); also cond_h tmp
__device__ __half g_uh [TOK * HID];          // silu out (fp16); also x_h tmp

#define OFF_PATCH 0
#define OFF_COND  786432
#define OFF_QKV   1835008
#define OFF_WO    39583744
#define OFF_W1    52166656
#define OFF_W2    86769664
#define OFF_W3    121372672

// ---------------- helpers ----------------
__device__ __forceinline__ void cp_async16(const void* smem, const void* gmem, bool pred) {
    unsigned s = (unsigned)__cvta_generic_to_shared(smem);
    if (pred)
        asm volatile("cp.async.cg.shared.global [%0], [%1], 16;" :: "r"(s), "l"(gmem));
}
__device__ __forceinline__ void cp_commit() { asm volatile("cp.async.commit_group;" ::); }
template<int N>
__device__ __forceinline__ void cp_wait() { asm volatile("cp.async.wait_group %0;" :: "n"(N)); }

__device__ __forceinline__ void mma_f16(float* c, const unsigned* a, const unsigned* b) {
    asm volatile(
        "mma.sync.aligned.m16n8k16.row.col.f32.f16.f16.f32 "
        "{%0,%1,%2,%3}, {%4,%5,%6,%7}, {%8,%9}, {%0,%1,%2,%3};"
        : "+f"(c[0]), "+f"(c[1]), "+f"(c[2]), "+f"(c[3])
        : "r"(a[0]), "r"(a[1]), "r"(a[2]), "r"(a[3]), "r"(b[0]), "r"(b[1]));
}

// ---------------- FP16 tensor-core GEMM ----------------
// C[M,N] = A[M,K] @ BT[N,K]^T (+C if ACC). A,BT fp16 K-major; C fp32.
// CTA 128x256x32, 8 warps (2x4) of 64x64, m16n8k16, 4-stage cp.async.
#define TBM 128
#define TBN 256
#define TBK 32
#define SLDH 40                    // smem row stride in halves (32 + 8 pad)
#define SA_H (TBM * SLDH)          // 5120 halves
#define SB_H (TBN * SLDH)          // 10240 halves
#define STG_H (SA_H + SB_H)        // 15360 halves
#define TNSTG 4
#define TSMEM (TNSTG * STG_H * 2)  // 122880 bytes

template<bool ACC>
__global__ __launch_bounds__(256, 1)
void hgemm(const __half* __restrict__ A, const __half* __restrict__ BT,
           float* __restrict__ C, int M, int N, int K) {
    extern __shared__ __half sm[];

    const int tid = threadIdx.x;
    const int warp = tid >> 5, lane = tid & 31;
    const int wm = warp & 1, wn = warp >> 1;        // 2 x 4 warps of 64x64
    const int gid = lane >> 2, tig = lane & 3;
    const int bm = blockIdx.y * TBM, bn = blockIdx.x * TBN;

    const int a_row = tid >> 1;                     // 0..127
    const int a_off = (tid & 1) * 16;               // halves
    const bool a_ok = (bm + a_row) < M;
    const __half* Ag = A + (size_t)(bm + a_row) * K + a_off;
    const __half* Bg = BT + (size_t)(bn + tid) * K;

    float acc[4][8][4];
    #pragma unroll
    for (int i = 0; i < 4; i++)
        #pragma unroll
        for (int j = 0; j < 8; j++)
            #pragma unroll
            for (int r = 0; r < 4; r++) acc[i][j][r] = 0.f;

    const int nk = K / TBK;

    auto load_stage = [&](int kt, int s) {
        __half* As = sm + s * STG_H;
        __half* Bs = As + SA_H;
        const __half* ag = Ag + kt * TBK;
        __half* ad = As + a_row * SLDH + a_off;
        cp_async16(ad, ag, a_ok);
        cp_async16(ad + 8, ag + 8, a_ok);
        const __half* bg = Bg + kt * TBK;
        __half* bd = Bs + tid * SLDH;
        #pragma unroll
        for (int c = 0; c < 4; c++) cp_async16(bd + c * 8, bg + c * 8, true);
    };

    #pragma unroll
    for (int s = 0; s < TNSTG - 1; s++) {
        if (s < nk) load_stage(s, s);
        cp_commit();
    }

    for (int kt = 0; kt < nk; kt++) {
        const int s = kt % TNSTG;
        cp_wait<TNSTG - 2>();
        __syncthreads();
        if (kt + TNSTG - 1 < nk) load_stage(kt + TNSTG - 1, (kt + TNSTG - 1) % TNSTG);
        cp_commit();

        const __half* Ab = sm + s * STG_H;
        const __half* Bb = Ab + SA_H;

        #pragma unroll
        for (int ks = 0; ks < 2; ks++) {
            const int k0 = ks * 16;
            unsigned afr[16], bfr[16];
            #pragma unroll
            for (int mt = 0; mt < 4; mt++) {
                const int m = wm * 64 + mt * 16 + gid;
                const __half* p0 = Ab + m * SLDH + k0 + 2 * tig;
                afr[mt*4+0] = *(const unsigned*)(p0);
                afr[mt*4+1] = *(const unsigned*)(p0 + 8 * SLDH);
                afr[mt*4+2] = *(const unsigned*)(p0 + 8);
                afr[mt*4+3] = *(const unsigned*)(p0 + 8 * SLDH + 8);
            }
            #pragma unroll
            for (int nt = 0; nt < 8; nt++) {
                const int n = wn * 64 + nt * 8 + gid;
                const __half* p0 = Bb + n * SLDH + k0 + 2 * tig;
                bfr[nt*2+0] = *(const unsigned*)(p0);
                bfr[nt*2+1] = *(const unsigned*)(p0 + 8);
            }
            #pragma unroll
            for (int mt = 0; mt < 4; mt++)
                #pragma unroll
                for (int nt = 0; nt < 8; nt++)
                    mma_f16(acc[mt][nt], &afr[mt * 4], &bfr[nt * 2]);
        }
    }

    // epilogue
    #pragma unroll
    for (int mt = 0; mt < 4; mt++) {
        #pragma unroll
        for (int nt = 0; nt < 8; nt++) {
            const float* c = acc[mt][nt];
            const int mg = bm + wm * 64 + mt * 16 + gid;
            const int ng = bn + wn * 64 + nt * 8 + 2 * tig;
            if (mg < M) {
                float2* p = (float2*)(C + (size_t)mg * N + ng);
                if (ACC) { float2 t = *p; t.x += c[0]; t.y += c[1]; *p = t; }
                else     { *p = make_float2(c[0], c[1]); }
            }
            if (mg + 8 < M) {
                float2* p = (float2*)(C + (size_t)(mg + 8) * N + ng);
                if (ACC) { float2 t = *p; t.x += c[2]; t.y += c[3]; *p = t; }
                else     { *p = make_float2(c[2], c[3]); }
            }
        }
    }
}

// ---------------- weight prep: transpose + fp16 convert ----------------
__global__ void wprep_kernel(const float* __restrict__ W, __half* __restrict__ WT, int K, int N) {
    __shared__ float t[32][33];
    const size_t lo = (size_t)blockIdx.z * K * N;
    const float* Wp = W + lo;
    __half* Tp = WT + lo;
    const int k0 = blockIdx.y * 32, n0 = blockIdx.x * 32;
    const int x = threadIdx.x, y = threadIdx.y;
    #pragma unroll
    for (int i = 0; i < 32; i += 8)
        t[y + i][x] = Wp[(size_t)(k0 + y + i) * N + (n0 + x)];
    __syncthreads();
    #pragma unroll
    for (int i = 0; i < 32; i += 8)
        Tp[(size_t)(n0 + y + i) * K + (k0 + x)] = __float2half_rn(t[x][y + i]);
}

__global__ void round_half_kernel(const float* __restrict__ in, __half* __restrict__ out, int n4) {
    int i = blockIdx.x * blockDim.x + threadIdx.x;
    if (i >= n4) return;
    float4 v = ((const float4*)in)[i];
    __half2 h0 = __floats2half2_rn(v.x, v.y);
    __half2 h1 = __floats2half2_rn(v.z, v.w);
    ((uint2*)out)[i] = make_uint2(*(unsigned*)&h0, *(unsigned*)&h1);
}

// ---------------- block reduce ----------------
__device__ __forceinline__ float block_reduce_sum(float v, float* red) {
    int tid = threadIdx.x;
    #pragma unroll
    for (int o = 16; o; o >>= 1) v += __shfl_xor_sync(0xffffffffu, v, o);
    if ((tid & 31) == 0) red[tid >> 5] = v;
    __syncthreads();
    if (tid < 8) {
        float w = red[tid];
        #pragma unroll
        for (int o = 4; o; o >>= 1) w += __shfl_xor_sync(0xffu, w, o);
        if (tid == 0) red[0] = w;
    }
    __syncthreads();
    float r = red[0];
    __syncthreads();
    return r;
}

// ---------------- freqs_cis table ----------------
__global__ void fc_kernel(float2* __restrict__ fc) {
    int idx = blockIdx.x * blockDim.x + threadIdx.x;
    if (idx >= SEQ * 32) return;
    int s = idx / 32, i = idx % 32;
    if (s == 0) { fc[idx] = make_float2(0.f, 0.f); return; }
    int sp = s - 1;
    int gy = sp / 16, gx = sp % 16;
    int j   = (i < 16) ? i  : i - 16;
    int pos = (i < 16) ? gy : gx;
    float fr  = powf(10000.f, -(float)j / 16.f);
    float ang = (float)pos * fr;
    fc[idx] = make_float2(cosf(ang), sinf(ang));
}

// ---------------- assemble + LayerNorm ----------------
__global__ __launch_bounds__(256)
void assemble_ln(const float* __restrict__ tmpA, const float* __restrict__ tmpC,
                 const float* __restrict__ patch_b, const float* __restrict__ cond_b,
                 const float* __restrict__ pos, const float* __restrict__ g,
                 const float* __restrict__ bb, float* __restrict__ h) {
    __shared__ float red[8];
    int t = blockIdx.x;
    int b = t / SEQ, s = t % SEQ;
    int tid = threadIdx.x;
    float4 v;
    if (s == 0) {
        v = *((const float4*)(tmpC + (size_t)b * EMBED) + tid);
        float4 cb = ((const float4*)cond_b)[tid];
        v.x += cb.x; v.y += cb.y; v.z += cb.z; v.w += cb.w;
    } else {
        v = *((const float4*)(tmpA + (size_t)(b * 256 + s - 1) * EMBED) + tid);
        float4 pb = ((const float4*)patch_b)[tid];
        v.x += pb.x; v.y += pb.y; v.z += pb.z; v.w += pb.w;
    }
    float4 pe = *((const float4*)(pos + (size_t)s * EMBED) + tid);
    v.x += pe.x; v.y += pe.y; v.z += pe.z; v.w += pe.w;

    float sum  = block_reduce_sum(v.x + v.y + v.z + v.w, red);
    float mean = sum * (1.f / EMBED);
    float dx = v.x - mean, dy = v.y - mean, dz = v.z - mean, dw = v.w - mean;
    float ss  = block_reduce_sum(dx * dx + dy * dy + dz * dz + dw * dw, red);
    float r   = rsqrtf(ss * (1.f / EMBED) + 1e-6f);
    float4 gv = ((const float4*)g)[tid];
    float4 bv = ((const float4*)bb)[tid];
    float4 o  = make_float4(dx * r * gv.x + bv.x, dy * r * gv.y + bv.y,
                            dz * r * gv.z + bv.z, dw * r * gv.w + bv.w);
    *((float4*)(h + (size_t)t * EMBED) + tid) = o;
}

// ---------------- RMSNorm (fp16 out) ----------------
__global__ __launch_bounds__(256)
void rmsnorm_kernel(const float* __restrict__ h, const float* __restrict__ w,
                    __half* __restrict__ out) {
    __shared__ float red[8];
    int t = blockIdx.x, tid = threadIdx.x;
    float4 v = *((const float4*)(h + (size_t)t * EMBED) + tid);
    float ss = block_reduce_sum(v.x * v.x + v.y * v.y + v.z * v.z + v.w * v.w, red);
    float r  = rsqrtf(ss * (1.f / EMBED) + 1e-5f);
    float4 wv = ((const float4*)w)[tid];
    __half2 h0 = __floats2half2_rn(v.x * r * wv.x, v.y * r * wv.y);
    __half2 h1 = __floats2half2_rn(v.z * r * wv.z, v.w * r * wv.w);
    ((uint2*)(out + (size_t)t * EMBED))[tid] = make_uint2(*(unsigned*)&h0, *(unsigned*)&h1);
}

// ---------------- RoPE ----------------
__global__ void rope_kernel(float* __restrict__ qkv, const float2* __restrict__ fc) {
    int idx = blockIdx.x * blockDim.x + threadIdx.x;
    if (idx >= TOK * 512) return;
    int t = idx >> 9;
    int r = idx & 511;
    int head = r >> 5, pair = r & 31;
    int s = t % SEQ;
    float2 cs = fc[s * 32 + pair];
    size_t base = (size_t)t * (3 * EMBED) + head * HDIM + pair * 2;
    float2* qp = (float2*)(qkv + base);
    float2 xv = *qp;
    *qp = make_float2(xv.x * cs.x - xv.y * cs.y, xv.y * cs.x + xv.x * cs.y);
    float2* kp = (float2*)(qkv + base + EMBED);
    xv = *kp;
    *kp = make_float2(xv.x * cs.x - xv.y * cs.y, xv.y * cs.x + xv.x * cs.y);
}

// ---------------- attention (fp32 math, fp16 out) ----------------
#define KV_STRIDE 65
#define ATTN_SMEM ((2 * SEQ * KV_STRIDE + 8 * HDIM) * 4)

__global__ __launch_bounds__(256)
void attn_kernel(const float* __restrict__ qkv, __half* __restrict__ out) {
    extern __shared__ float smv[];
    float* Ks = smv;
    float* Vs = smv + SEQ * KV_STRIDE;
    float* Qs = Vs + SEQ * KV_STRIDE;

    const int h = blockIdx.x;
    const int b = blockIdx.y;
    const int tid = threadIdx.x;

    for (int i = tid; i < SEQ * HDIM; i += 256) {
        int t = i >> 6, d = i & 63;
        size_t row = (size_t)(b * SEQ + t) * (3 * EMBED) + h * HDIM + d;
        Ks[t * KV_STRIDE + d] = qkv[row + EMBED];
        Vs[t * KV_STRIDE + d] = qkv[row + 2 * EMBED];
    }
    __syncthreads();

    const int w = tid >> 5, lane = tid & 31;

    for (int q = w; q < SEQ; q += 8) {
        size_t qrow = (size_t)(b * SEQ + q) * (3 * EMBED) + h * HDIM;
        Qs[w * HDIM + lane]      = qkv[qrow + lane];
        Qs[w * HDIM + lane + 32] = qkv[qrow + lane + 32];
        __syncwarp();

        const int nk = q + 1;
        const int nchunk = (nk + 31) >> 5;
        float s_loc[9];
        #pragma unroll
        for (int j = 0; j < 9; j++) s_loc[j] = -1e30f;

        const float* qp = Qs + w * HDIM;
        #pragma unroll 1
        for (int j = 0; j < nchunk; j++) {
            int key = j * 32 + lane;
            if (key < nk) {
                const float* kp = Ks + key * KV_STRIDE;
                float s = 0.f;
                #pragma unroll
                for (int d = 0; d < 64; d++) s = fmaf(qp[d], kp[d], s);
                s_loc[j] = s * 0.125f;
            }
        }

        float m = -1e30f;
        #pragma unroll
        for (int j = 0; j < 9; j++) if (j < nchunk) m = fmaxf(m, s_loc[j]);
        #pragma unroll
        for (int o = 16; o; o >>= 1) m = fmaxf(m, __shfl_xor_sync(0xffffffffu, m, o));

        float l = 0.f;
        #pragma unroll
        for (int j = 0; j < 9; j++) {
            if (j < nchunk) {
                s_loc[j] = __expf(s_loc[j] - m);
                l += s_loc[j];
            }
        }
        #pragma unroll
        for (int o = 16; o; o >>= 1) l += __shfl_xor_sync(0xffffffffu, l, o);
        float inv = 1.f / l;

        float o0 = 0.f, o1 = 0.f;
        #pragma unroll 1
        for (int j = 0; j < nchunk; j++) {
            float sj = s_loc[j];
            int kbase = j * 32;
            int cnt = nk - kbase; if (cnt > 32) cnt = 32;
            for (int src = 0; src < cnt; src++) {
                float p = __shfl_sync(0xffffffffu, sj, src);
                const float* vp = Vs + (kbase + src) * KV_STRIDE;
                o0 = fmaf(p, vp[lane],      o0);
                o1 = fmaf(p, vp[lane + 32], o1);
            }
        }
        size_t orow = (size_t)(b * SEQ + q) * EMBED + h * HDIM;
        out[orow + lane]      = __float2half_rn(o0 * inv);
        out[orow + lane + 32] = __float2half_rn(o1 * inv);
        __syncwarp();
    }
}

// ---------------- SiLU(u) * v -> fp16 ----------------
__global__ void silu_mul_kernel(const float* __restrict__ u, const float* __restrict__ v,
                                __half* __restrict__ out, int n4) {
    int idx = blockIdx.x * blockDim.x + threadIdx.x;
    if (idx >= n4) return;
    float4 uu = ((const float4*)u)[idx];
    float4 vv = ((const float4*)v)[idx];
    float a = uu.x / (1.f + __expf(-uu.x)) * vv.x;
    float b = uu.y / (1.f + __expf(-uu.y)) * vv.y;
    float c = uu.z / (1.f + __expf(-uu.z)) * vv.z;
    float d = uu.w / (1.f + __expf(-uu.w)) * vv.w;
    __half2 h0 = __floats2half2_rn(a, b);
    __half2 h1 = __floats2half2_rn(c, d);
    ((uint2*)out)[idx] = make_uint2(*(unsigned*)&h0, *(unsigned*)&h1);
}

// ---------------- host ----------------
static inline dim3 tc_grid(int M, int N) {
    return dim3(N / TBN, (M + TBM - 1) / TBM);
}

extern "C" void kernel_launch(void* const* d_in, const int* in_sizes, int n_in,
                              void* d_out, int out_size) {
    const float* x        = (const float*)d_in[0];
    const float* cond     = (const float*)d_in[1];
    const float* patch_w  = (const float*)d_in[2];
    const float* patch_b  = (const float*)d_in[3];
    const float* ln_g     = (const float*)d_in[4];
    const float* ln_b     = (const float*)d_in[5];
    const float* pos      = (const float*)d_in[6];
    const float* cond_w   = (const float*)d_in[7];
    const float* cond_b   = (const float*)d_in[8];
    const float* wqkv     = (const float*)d_in[9];
    const float* wo       = (const float*)d_in[10];
    const float* w1       = (const float*)d_in[11];
    const float* w2       = (const float*)d_in[12];
    const float* w3       = (const float*)d_in[13];
    const float* anw      = (const float*)d_in[14];
    const float* fnw      = (const float*)d_in[15];

    float *h, *qkv, *ct, *u, *v; float2* fc;
    __half *wh, *ah, *aoh, *uh;
    cudaGetSymbolAddress((void**)&h,   g_h);
    cudaGetSymbolAddress((void**)&qkv, g_qkv);
    cudaGetSymbolAddress((void**)&ct,  g_ct);
    cudaGetSymbolAddress((void**)&u,   g_u);
    cudaGetSymbolAddress((void**)&v,   g_v);
    cudaGetSymbolAddress((void**)&fc,  g_fc);
    cudaGetSymbolAddress((void**)&wh,  g_wh);
    cudaGetSymbolAddress((void**)&ah,  g_ah);
    cudaGetSymbolAddress((void**)&aoh, g_aoh);
    cudaGetSymbolAddress((void**)&uh,  g_uh);

    cudaFuncSetAttribute(attn_kernel,  cudaFuncAttributeMaxDynamicSharedMemorySize, ATTN_SMEM);
    cudaFuncSetAttribute(hgemm<false>, cudaFuncAttributeMaxDynamicSharedMemorySize, TSMEM);
    cudaFuncSetAttribute(hgemm<true>,  cudaFuncAttributeMaxDynamicSharedMemorySize, TSMEM);

    dim3 tb(32, 8);
    // weights: transpose [K,N] -> [N,K] + fp16 convert
    wprep_kernel<<<dim3(1024/32, 768/32, 1),  tb>>>(patch_w, wh + OFF_PATCH, 768, 1024);
    wprep_kernel<<<dim3(1024/32, 1024/32, 1), tb>>>(cond_w,  wh + OFF_COND,  1024, 1024);
    wprep_kernel<<<dim3(3072/32, 1024/32, NB), tb>>>(wqkv,   wh + OFF_QKV,   1024, 3072);
    wprep_kernel<<<dim3(1024/32, 1024/32, NB), tb>>>(wo,     wh + OFF_WO,    1024, 1024);
    wprep_kernel<<<dim3(2816/32, 1024/32, NB), tb>>>(w1,     wh + OFF_W1,    1024, 2816);
    wprep_kernel<<<dim3(1024/32, 2816/32, NB), tb>>>(w2,     wh + OFF_W2,    2816, 1024);
    wprep_kernel<<<dim3(2816/32, 1024/32, NB), tb>>>(w3,     wh + OFF_W3,    1024, 2816);
    // inputs -> fp16
    round_half_kernel<<<(PTOK*768/4 + 255)/256, 256>>>(x, uh, PTOK*768/4);
    round_half_kernel<<<(BATCH*EMBED/4 + 255)/256, 256>>>(cond, aoh, BATCH*EMBED/4);

    fc_kernel<<<(SEQ * 32 + 255) / 256, 256>>>(fc);

    // prelude
    hgemm<false><<<tc_grid(PTOK, EMBED), 256, TSMEM>>>(uh, wh + OFF_PATCH, qkv, PTOK, EMBED, 768);
    hgemm<false><<<tc_grid(BATCH, EMBED), 256, TSMEM>>>(aoh, wh + OFF_COND, ct, BATCH, EMBED, EMBED);
    assemble_ln<<<TOK, 256>>>(qkv, ct, patch_b, cond_b, pos, ln_g, ln_b, h);

    for (int l = 0; l < NB; l++) {
        const __half* wqkv_l = wh + OFF_QKV + (size_t)l * EMBED * 3 * EMBED;
        const __half* wo_l   = wh + OFF_WO  + (size_t)l * EMBED * EMBED;
        const __half* w1_l   = wh + OFF_W1  + (size_t)l * EMBED * HID;
        const __half* w2_l   = wh + OFF_W2  + (size_t)l * HID * EMBED;
        const __half* w3_l   = wh + OFF_W3  + (size_t)l * EMBED * HID;

        rmsnorm_kernel<<<TOK, 256>>>(h, anw + (size_t)l * EMBED, ah);
        hgemm<false><<<tc_grid(TOK, 3 * EMBED), 256, TSMEM>>>(ah, wqkv_l, qkv, TOK, 3 * EMBED, EMBED);
        rope_kernel<<<(TOK * 512 + 255) / 256, 256>>>(qkv, fc);
        attn_kernel<<<dim3(HEADS, BATCH), 256, ATTN_SMEM>>>(qkv, aoh);
        hgemm<true><<<tc_grid(TOK, EMBED), 256, TSMEM>>>(aoh, wo_l, h, TOK, EMBED, EMBED);

        rmsnorm_kernel<<<TOK, 256>>>(h, fnw + (size_t)l * EMBED, ah);
        hgemm<false><<<tc_grid(TOK, HID), 256, TSMEM>>>(ah, w1_l, u, TOK, HID, EMBED);
        hgemm<false><<<tc_grid(TOK, HID), 256, TSMEM>>>(ah, w3_l, v, TOK, HID, EMBED);
        silu_mul_kernel<<<(TOK * HID / 4 + 255) / 256, 256>>>(u, v, uh, TOK * HID / 4);
        hgemm<true><<<tc_grid(TOK, EMBED), 256, TSMEM>>>(uh, w2_l, h, TOK, EMBED, HID);
    }

    cudaMemcpyAsync(d_out, h, (size_t)TOK * EMBED * sizeof(float),
                    cudaMemcpyDeviceToDevice);
}